// round 5
// baseline (speedup 1.0000x reference)
#include <cuda_runtime.h>

#define BATCH 4
#define NPTS  4096
#define KPN   512
#define KNN   32

#define GDIM   32
#define NCELLS (GDIM * GDIM * GDIM)      // 32768
#define NSB    (2 * BATCH)               // 8 (set,batch) grids
#define GRIDLO (-4.0f)
#define CELLH  (0.25f)
#define INVH   (4.0f)
#define INFV   1e30f

// set0 = tgt (gts), set1 = src_transformed (preds)
__device__ int    g_cnt[NSB * NCELLS];
__device__ int    g_start[NSB * NCELLS];
__device__ int    g_cursor[NSB * NCELLS];
__device__ int    g_cell[NSB * NPTS];
__device__ float4 g_pts[NSB * NPTS];

__device__ __forceinline__ int cell_of(float x, float y, float z) {
    int cx = (int)floorf((x - GRIDLO) * INVH);
    int cy = (int)floorf((y - GRIDLO) * INVH);
    int cz = (int)floorf((z - GRIDLO) * INVH);
    cx = min(GDIM - 1, max(0, cx));
    cy = min(GDIM - 1, max(0, cy));
    cz = min(GDIM - 1, max(0, cz));
    return (cz * GDIM + cy) * GDIM + cx;
}

__device__ __forceinline__ float block_reduce_sum(float v) {
    __shared__ float sh[32];
    int lane = threadIdx.x & 31;
    int wid  = threadIdx.x >> 5;
    #pragma unroll
    for (int o = 16; o; o >>= 1) v += __shfl_down_sync(0xffffffffu, v, o);
    if (lane == 0) sh[wid] = v;
    __syncthreads();
    if (wid == 0) {
        v = (lane < (int)(blockDim.x >> 5)) ? sh[lane] : 0.0f;
        #pragma unroll
        for (int o = 16; o; o >>= 1) v += __shfl_down_sync(0xffffffffu, v, o);
    }
    return v;
}

// ---------------------------------------------------------------------------
// K1: zero counts + outputs (state persists across graph replays!)
// ---------------------------------------------------------------------------
__global__ void zero_kernel(float* out) {
    int i = blockIdx.x * blockDim.x + threadIdx.x;   // 65536 threads
    #pragma unroll
    for (int u = 0; u < 4; u++) g_cnt[i + u * 65536] = 0;
    if (i == 0) { out[0] = 0.0f; out[1] = 0.0f; }
}

// ---------------------------------------------------------------------------
// K2: count points per cell, remember each point's cell.
// ---------------------------------------------------------------------------
__global__ void count_kernel(const float* __restrict__ tgt,
                             const float* __restrict__ src_tr) {
    int i = blockIdx.x * blockDim.x + threadIdx.x;   // 0..32767
    int sb  = i >> 12;                               // (set,batch)
    int set = sb >> 2;
    int b   = sb & 3;
    int p   = i & (NPTS - 1);
    const float* S = (set == 0 ? tgt : src_tr) + b * 3 * NPTS;
    float x = S[p], y = S[NPTS + p], z = S[2 * NPTS + p];
    int c = cell_of(x, y, z);
    g_cell[i] = c;
    atomicAdd(&g_cnt[sb * NCELLS + c], 1);
}

// ---------------------------------------------------------------------------
// K3: exclusive prefix sum per (set,batch) grid. 8 blocks x 256 threads,
// 128 cells per thread (seq sum -> block scan -> seq writeback).
// ---------------------------------------------------------------------------
__global__ void scan_kernel() {
    __shared__ int ssum[256];
    int sb = blockIdx.x;
    int t  = threadIdx.x;
    int base = sb * NCELLS + t * 128;

    int acc = 0;
    #pragma unroll 8
    for (int c = 0; c < 128; c++) acc += g_cnt[base + c];
    ssum[t] = acc;
    __syncthreads();
    // Hillis-Steele inclusive scan over 256
    #pragma unroll
    for (int off = 1; off < 256; off <<= 1) {
        int v = (t >= off) ? ssum[t - off] : 0;
        __syncthreads();
        ssum[t] += v;
        __syncthreads();
    }
    int running = ssum[t] - acc;  // exclusive prefix of this thread's chunk
    #pragma unroll 8
    for (int c = 0; c < 128; c++) {
        g_start[base + c]  = running;
        g_cursor[base + c] = running;
        running += g_cnt[base + c];
    }
}

// ---------------------------------------------------------------------------
// K4: scatter points into cell-sorted order.
// ---------------------------------------------------------------------------
__global__ void scatter_kernel(const float* __restrict__ tgt,
                               const float* __restrict__ src_tr) {
    int i = blockIdx.x * blockDim.x + threadIdx.x;   // 0..32767
    int sb  = i >> 12;
    int set = sb >> 2;
    int b   = sb & 3;
    int p   = i & (NPTS - 1);
    const float* S = (set == 0 ? tgt : src_tr) + b * 3 * NPTS;
    float x = S[p], y = S[NPTS + p], z = S[2 * NPTS + p];
    int c = g_cell[i];
    int pos = atomicAdd(&g_cursor[sb * NCELLS + c], 1);
    g_pts[sb * NPTS + pos] = make_float4(x, y, z, 0.0f);
}

// ---------------------------------------------------------------------------
// K5: fused query (ring-expanding NN search, cell-sorted query order) + nbh.
// Blocks 0..127: gal. Blocks 128..255: knn + keypoint loss.
// ---------------------------------------------------------------------------
__global__ void __launch_bounds__(256)
query_kernel(const float* __restrict__ sk,  const float* __restrict__ tk,
             const float* __restrict__ Rot, const float* __restrict__ Tr,
             const float* __restrict__ sknn, const float* __restrict__ tknn,
             float* __restrict__ out) {
    int blk = blockIdx.x;
    int t   = threadIdx.x;

    if (blk < 128) {
        // ---- gal: each thread = one cell-sorted query point ----
        int i   = blk * 256 + t;             // 0..32767
        int sbq = i >> 12;                   // query (set,batch)
        int qs  = sbq >> 2;
        int b   = sbq & 3;
        int j   = i & (NPTS - 1);
        int sbr = (1 - qs) * 4 + b;          // ref grid = other set, same batch

        float4 qp = g_pts[sbq * NPTS + j];
        float qx = qp.x, qy = qp.y, qz = qp.z;

        int cx = min(GDIM - 1, max(0, (int)floorf((qx - GRIDLO) * INVH)));
        int cy = min(GDIM - 1, max(0, (int)floorf((qy - GRIDLO) * INVH)));
        int cz = min(GDIM - 1, max(0, (int)floorf((qz - GRIDLO) * INVH)));

        const int*    cnt  = g_cnt   + sbr * NCELLS;
        const int*    strt = g_start + sbr * NCELLS;
        const float4* pts  = g_pts   + sbr * NPTS;

        float dmin = INFV;
        for (int k = 0; k < GDIM; k++) {
            int xl = max(cx - k, 0), xh = min(cx + k, GDIM - 1);
            int yl = max(cy - k, 0), yh = min(cy + k, GDIM - 1);
            int zl = max(cz - k, 0), zh = min(cz + k, GDIM - 1);
            for (int z = zl; z <= zh; z++) {
                int dz = abs(z - cz);
                for (int y = yl; y <= yh; y++) {
                    int m2 = max(dz, abs(y - cy));
                    for (int x = xl; x <= xh; x++) {
                        int ring = max(m2, abs(x - cx));
                        if (ring != k) continue;
                        int c = (z * GDIM + y) * GDIM + x;
                        int n = cnt[c];
                        if (!n) continue;
                        int s = strt[c];
                        for (int u = 0; u < n; u++) {
                            float4 P = pts[s + u];
                            float dx = qx - P.x, dy = qy - P.y, dzp = qz - P.z;
                            float d = fmaf(dx, dx, fmaf(dy, dy, dzp * dzp));
                            dmin = fminf(dmin, d);
                        }
                    }
                }
            }
            // stopping bound: distance from q to unsearched region
            float fx = fminf(xl > 0        ? qx - (GRIDLO + xl * CELLH)       : INFV,
                             xh < GDIM - 1 ? (GRIDLO + (xh + 1) * CELLH) - qx : INFV);
            float fy = fminf(yl > 0        ? qy - (GRIDLO + yl * CELLH)       : INFV,
                             yh < GDIM - 1 ? (GRIDLO + (yh + 1) * CELLH) - qy : INFV);
            float fz = fminf(zl > 0        ? qz - (GRIDLO + zl * CELLH)       : INFV,
                             zh < GDIM - 1 ? (GRIDLO + (zh + 1) * CELLH) - qz : INFV);
            float r = fmaxf(0.0f, fminf(fx, fminf(fy, fz)));
            if (dmin <= r * r) break;
        }

        const float c = 0.01f;
        float h = (dmin < c) ? (0.5f * dmin * dmin) : fmaf(c, dmin, -0.5f * c * c);
        float s = block_reduce_sum(h);
        if (t == 0) atomicAdd(&out[1], s);
    } else {
        // ---- nbh: knn L2 / K + keypoint transform loss ----
        int i = (blk - 128) * 256 + t;       // 0..32767
        const int TOT4 = BATCH * 3 * KPN * KNN / 4;  // 49152
        const float4* s4 = (const float4*)sknn;
        const float4* t4 = (const float4*)tknn;
        float acc = 0.0f;
        for (int jj = i; jj < TOT4; jj += 32768) {
            float4 a = s4[jj], bb = t4[jj];
            float d0 = a.x - bb.x, d1 = a.y - bb.y, d2 = a.z - bb.z, d3 = a.w - bb.w;
            acc = fmaf(d0, d0, fmaf(d1, d1, fmaf(d2, d2, fmaf(d3, d3, acc))));
        }
        acc *= (1.0f / (float)KNN);

        if (i < BATCH * KPN) {
            int kb = i >> 9;
            int p  = i & (KPN - 1);
            const float* Rb  = Rot + kb * 9;
            const float* tb  = Tr + kb * 3;
            const float* skb = sk + kb * 3 * KPN;
            const float* tkb = tk + kb * 3 * KPN;
            float px = skb[p], py = skb[KPN + p], pz = skb[2 * KPN + p];
            #pragma unroll
            for (int cd = 0; cd < 3; cd++) {
                float w = fmaf(Rb[cd * 3 + 0], px,
                          fmaf(Rb[cd * 3 + 1], py,
                          fmaf(Rb[cd * 3 + 2], pz, tb[cd])))
                          - tkb[cd * KPN + p];
                acc = fmaf(w, w, acc);
            }
        }
        float s = block_reduce_sum(acc);
        if (t == 0) atomicAdd(&out[0], s);
    }
}

// ---------------------------------------------------------------------------
extern "C" void kernel_launch(void* const* d_in, const int* in_sizes, int n_in,
                              void* d_out, int out_size) {
    const float* src_kp  = (const float*)d_in[0];  // (B,3,KP)
    const float* tgt_kp  = (const float*)d_in[1];  // (B,3,KP)
    const float* rot     = (const float*)d_in[2];  // (B,3,3)
    const float* tra     = (const float*)d_in[3];  // (B,3)
    const float* src_knn = (const float*)d_in[4];  // (B,3,KP,K)
    const float* tgt_knn = (const float*)d_in[5];  // (B,3,KP,K)
    // d_in[6] = k (constant 32, hardcoded)
    const float* src_tr  = (const float*)d_in[7];  // (B,3,N) preds
    const float* tgt     = (const float*)d_in[8];  // (B,3,N) gts
    float* out = (float*)d_out;                    // out[0]=nbh, out[1]=gal

    zero_kernel<<<256, 256>>>(out);
    count_kernel<<<128, 256>>>(tgt, src_tr);
    scan_kernel<<<NSB, 256>>>();
    scatter_kernel<<<128, 256>>>(tgt, src_tr);
    query_kernel<<<256, 256>>>(src_kp, tgt_kp, rot, tra, src_knn, tgt_knn, out);
}

// round 6
// speedup vs baseline: 21.7988x; 21.7988x over previous
#include <cuda_runtime.h>

#define BATCH 4
#define NPTS  4096
#define KPN   512
#define KNN   32

#define TPB   256
#define BSL   64              // refs staged per block
#define NBS   (NPTS / BSL)    // 64
#define ATILE 2048            // queries per block (8 per thread)
#define NAT   (NPTS / ATILE)  // 2
#define INFV  3.0e38f

// Encoded global mins: [0,16384) = per-tgt-point (row) mins,
// [16384,32768) = per-src-point (col) mins.
// Stored value = descending order-preserving encoding, so atomicMax == float-min
// and 0 == "empty". Zero-initialized at module load; fin_kernel re-zeros each
// entry right after reading it (thread-local RAW), so every kernel_launch call
// starts from identical state (determinism + graph replay safe).
__device__ unsigned g_minbits[2 * BATCH * NPTS];

// Descending order-preserving float->uint encoding (max picks the float min).
__device__ __forceinline__ unsigned enc_desc(float f) {
    unsigned u = __float_as_uint(f);
    // ascending enc: neg -> ~u ; pos -> u | 0x80000000. Descending = bitwise NOT.
    return (u & 0x80000000u) ? u : ~(u | 0x80000000u);
}
__device__ __forceinline__ float dec_desc(unsigned e) {
    unsigned s = ~e;  // ascending encoding
    unsigned u = (s & 0x80000000u) ? (s ^ 0x80000000u) : ~s;
    return __uint_as_float(u);
}

// Packed f32x2 ops (sm_103a, PTX-only)
__device__ __forceinline__ float2 ffma2(float2 a, float2 b, float2 c) {
    float2 d;
    asm("fma.rn.f32x2 %0, %1, %2, %3;"
        : "=l"(*reinterpret_cast<unsigned long long*>(&d))
        : "l"(*reinterpret_cast<const unsigned long long*>(&a)),
          "l"(*reinterpret_cast<const unsigned long long*>(&b)),
          "l"(*reinterpret_cast<const unsigned long long*>(&c)));
    return d;
}
__device__ __forceinline__ float2 fadd2(float2 a, float2 b) {
    float2 d;
    asm("add.rn.f32x2 %0, %1, %2;"
        : "=l"(*reinterpret_cast<unsigned long long*>(&d))
        : "l"(*reinterpret_cast<const unsigned long long*>(&a)),
          "l"(*reinterpret_cast<const unsigned long long*>(&b)));
    return d;
}

// ---------------------------------------------------------------------------
// Kernel 1: fused tile pass. Block = A-tile (2048 queries, 8/thread in regs)
// x B-slice (64 refs in smem). Full squared distances computed ONCE; row mins
// kept in regs, col mins in per-warp smem (skewed index: conflict/race free).
// Final per-block mins folded into g_minbits via encoded atomicMax (RED.MAX).
// grid = BATCH * NAT * NBS = 512 blocks x 256 threads = 4096 warps (~27/SM).
// ---------------------------------------------------------------------------
__global__ void __launch_bounds__(TPB) min_kernel(const float* __restrict__ A,
                                                  const float* __restrict__ B,
                                                  float* __restrict__ out) {
    __shared__ float4 sB1[BSL];        // (bx,bx,by,by)
    __shared__ float4 sB2[BSL];        // (bz,bz,bn,bn)
    __shared__ float  cmin[8][BSL];    // per-warp col partial mins

    int bid = blockIdx.x;
    int bs  = bid & (NBS - 1);         // B slice 0..63
    int at  = (bid >> 6) & (NAT - 1);  // A tile 0..1
    int b   = bid >> 7;                // batch

    int t = threadIdx.x;
    int w = t >> 5;
    if (bid == 0 && t == 0) { out[0] = 0.0f; out[1] = 0.0f; }

    const float* Ab = A + b * 3 * NPTS;  // gts (tgt)
    const float* Bb = B + b * 3 * NPTS;  // preds (src_transformed)

    if (t < BSL) {
        int j = bs * BSL + t;
        float bx = Bb[j], by = Bb[NPTS + j], bz = Bb[2 * NPTS + j];
        float bn = fmaf(bx, bx, fmaf(by, by, bz * bz));
        sB1[t] = make_float4(bx, bx, by, by);
        sB2[t] = make_float4(bz, bz, bn, bn);
    }
    for (int idx = t; idx < 8 * BSL; idx += TPB) (&cmin[0][0])[idx] = INFV;
    __syncthreads();

    // 8 queries per thread as 4 packed pairs; x/y/z pre-scaled by -2, norm kept.
    float2 qx[4], qy[4], qz[4], qn[4];
    float  m[8];
    int i0 = at * ATILE + t;
    #pragma unroll
    for (int jp = 0; jp < 4; jp++) {
        int ia = i0 + (2 * jp) * TPB;
        int ic = i0 + (2 * jp + 1) * TPB;
        float ax = Ab[ia], ay = Ab[NPTS + ia], az = Ab[2 * NPTS + ia];
        float cx = Ab[ic], cy = Ab[NPTS + ic], cz = Ab[2 * NPTS + ic];
        float na = fmaf(ax, ax, fmaf(ay, ay, az * az));
        float nc = fmaf(cx, cx, fmaf(cy, cy, cz * cz));
        qx[jp] = make_float2(-2.0f * ax, -2.0f * cx);
        qy[jp] = make_float2(-2.0f * ay, -2.0f * cy);
        qz[jp] = make_float2(-2.0f * az, -2.0f * cz);
        qn[jp] = make_float2(na, nc);
        m[2 * jp] = INFV; m[2 * jp + 1] = INFV;
    }

    #pragma unroll 4
    for (int i = 0; i < BSL; i++) {
        int r = (t + i) & (BSL - 1);   // skewed: warp lanes hit distinct refs/banks
        float4 b1 = sB1[r];
        float4 b2 = sB2[r];
        float2 rx = make_float2(b1.x, b1.y);
        float2 ry = make_float2(b1.z, b1.w);
        float2 rz = make_float2(b2.x, b2.y);
        float2 rn = make_float2(b2.z, b2.w);

        float p[4];
        #pragma unroll
        for (int jp = 0; jp < 4; jp++) {
            float2 bias = fadd2(qn[jp], rn);  // qn + rn: full-dist bias
            float2 d2 = ffma2(qx[jp], rx, ffma2(qy[jp], ry, ffma2(qz[jp], rz, bias)));
            m[2 * jp]     = fminf(m[2 * jp],     d2.x);
            m[2 * jp + 1] = fminf(m[2 * jp + 1], d2.y);
            p[jp] = fminf(d2.x, d2.y);
        }
        float v = fminf(fminf(p[0], p[1]), fminf(p[2], p[3]));
        cmin[w][r] = fminf(cmin[w][r], v);
    }
    __syncthreads();

    // Row mins: encoded max-reduce (compiles to RED, no return value used).
    unsigned* rowm = g_minbits + b * NPTS;
    #pragma unroll
    for (int u = 0; u < 8; u++)
        atomicMax(&rowm[i0 + u * TPB], enc_desc(m[u]));

    // Col mins: merge 8 warp arrays, one atomic per B-point of this slice.
    if (t < BSL) {
        float cv = cmin[0][t];
        #pragma unroll
        for (int ww = 1; ww < 8; ww++) cv = fminf(cv, cmin[ww][t]);
        atomicMax(&g_minbits[BATCH * NPTS + b * NPTS + bs * BSL + t], enc_desc(cv));
    }
}

// ---------------------------------------------------------------------------
__device__ __forceinline__ float2 block_reduce2(float2 v) {
    __shared__ float2 sh[32];
    int lane = threadIdx.x & 31;
    int wid  = threadIdx.x >> 5;
    #pragma unroll
    for (int o = 16; o; o >>= 1) {
        v.x += __shfl_down_sync(0xffffffffu, v.x, o);
        v.y += __shfl_down_sync(0xffffffffu, v.y, o);
    }
    if (lane == 0) sh[wid] = v;
    __syncthreads();
    if (wid == 0) {
        v = (lane < (int)(blockDim.x >> 5)) ? sh[lane] : make_float2(0.0f, 0.0f);
        #pragma unroll
        for (int o = 16; o; o >>= 1) {
            v.x += __shfl_down_sync(0xffffffffu, v.x, o);
            v.y += __shfl_down_sync(0xffffffffu, v.y, o);
        }
    }
    return v;
}

// ---------------------------------------------------------------------------
// Kernel 2: finalize. One thread per min entry: decode, huber, sum; reset the
// entry to 0 for the next replay. Fused with knn L2 / K + keypoint loss.
// grid = 128 blocks x 256 threads = 32768.
// ---------------------------------------------------------------------------
__global__ void __launch_bounds__(256) fin_kernel(const float* __restrict__ sk,
                                                  const float* __restrict__ tk,
                                                  const float* __restrict__ Rot,
                                                  const float* __restrict__ Tr,
                                                  const float* __restrict__ sknn,
                                                  const float* __restrict__ tknn,
                                                  float* __restrict__ out) {
    int i = blockIdx.x * blockDim.x + threadIdx.x;  // 0..32767

    unsigned e = g_minbits[i];
    g_minbits[i] = 0;                  // reset empty state for next launch
    float d = dec_desc(e);
    const float c = 0.01f;
    float h = (d < c) ? (0.5f * d * d) : fmaf(c, d, -0.5f * c * c);

    // knn consensus (float4-vectorized)
    const int TOT4 = BATCH * 3 * KPN * KNN / 4;  // 49152
    const float4* s4 = (const float4*)sknn;
    const float4* t4 = (const float4*)tknn;
    float acc = 0.0f;
    for (int j = i; j < TOT4; j += 32768) {
        float4 a = s4[j], bb = t4[j];
        float d0 = a.x - bb.x, d1 = a.y - bb.y, d2 = a.z - bb.z, d3 = a.w - bb.w;
        acc = fmaf(d0, d0, fmaf(d1, d1, fmaf(d2, d2, fmaf(d3, d3, acc))));
    }
    acc *= (1.0f / (float)KNN);

    // keypoint transform loss
    if (i < BATCH * KPN) {
        int kb = i >> 9;
        int p  = i & (KPN - 1);
        const float* Rb  = Rot + kb * 9;
        const float* tb  = Tr + kb * 3;
        const float* skb = sk + kb * 3 * KPN;
        const float* tkb = tk + kb * 3 * KPN;
        float px = skb[p], py = skb[KPN + p], pz = skb[2 * KPN + p];
        #pragma unroll
        for (int cd = 0; cd < 3; cd++) {
            float wv = fmaf(Rb[cd * 3 + 0], px,
                       fmaf(Rb[cd * 3 + 1], py,
                       fmaf(Rb[cd * 3 + 2], pz, tb[cd])))
                       - tkb[cd * KPN + p];
            acc = fmaf(wv, wv, acc);
        }
    }

    float2 sums = block_reduce2(make_float2(acc, h));
    if (threadIdx.x == 0) {
        atomicAdd(&out[0], sums.x);
        atomicAdd(&out[1], sums.y);
    }
}

// ---------------------------------------------------------------------------
extern "C" void kernel_launch(void* const* d_in, const int* in_sizes, int n_in,
                              void* d_out, int out_size) {
    const float* src_kp  = (const float*)d_in[0];  // (B,3,KP)
    const float* tgt_kp  = (const float*)d_in[1];  // (B,3,KP)
    const float* rot     = (const float*)d_in[2];  // (B,3,3)
    const float* tra     = (const float*)d_in[3];  // (B,3)
    const float* src_knn = (const float*)d_in[4];  // (B,3,KP,K)
    const float* tgt_knn = (const float*)d_in[5];  // (B,3,KP,K)
    // d_in[6] = k (constant 32, hardcoded)
    const float* src_tr  = (const float*)d_in[7];  // (B,3,N) preds
    const float* tgt     = (const float*)d_in[8];  // (B,3,N) gts
    float* out = (float*)d_out;                    // out[0]=nbh, out[1]=gal

    // A = gts (tgt), B = preds (src_transformed); row+col mins cover both dirs.
    min_kernel<<<BATCH * NAT * NBS, TPB>>>(tgt, src_tr, out);
    fin_kernel<<<(2 * BATCH * NPTS) / 256, 256>>>(src_kp, tgt_kp, rot, tra,
                                                  src_knn, tgt_knn, out);
}

// round 7
// speedup vs baseline: 22.2762x; 1.0219x over previous
#include <cuda_runtime.h>

#define BATCH 4
#define NPTS  4096
#define KPN   512
#define KNN   32

#define TPB   256
#define BSL   128             // refs staged per block (loop length)
#define NBS   (NPTS / BSL)    // 32
#define ATILE 2048            // queries per block (8 per thread)
#define NAT   (NPTS / ATILE)  // 2
#define INFV  3.0e38f

// Encoded global mins: [0,16384) = per-tgt-point (row) mins,
// [16384,32768) = per-src-point (col) mins.
// Descending order-preserving encoding => atomicMax == float-min, 0 == empty.
// Zero at module load; fin_kernel re-zeros each entry after reading it, so
// every launch starts from identical state (determinism + graph replay safe).
__device__ unsigned g_minbits[2 * BATCH * NPTS];

__device__ __forceinline__ unsigned enc_desc(float f) {
    unsigned u = __float_as_uint(f);
    return (u & 0x80000000u) ? u : ~(u | 0x80000000u);
}
__device__ __forceinline__ float dec_desc(unsigned e) {
    unsigned s = ~e;
    unsigned u = (s & 0x80000000u) ? (s ^ 0x80000000u) : ~s;
    return __uint_as_float(u);
}

// Packed f32x2 ops (sm_103a, PTX-only)
__device__ __forceinline__ float2 ffma2(float2 a, float2 b, float2 c) {
    float2 d;
    asm("fma.rn.f32x2 %0, %1, %2, %3;"
        : "=l"(*reinterpret_cast<unsigned long long*>(&d))
        : "l"(*reinterpret_cast<const unsigned long long*>(&a)),
          "l"(*reinterpret_cast<const unsigned long long*>(&b)),
          "l"(*reinterpret_cast<const unsigned long long*>(&c)));
    return d;
}
__device__ __forceinline__ float2 fadd2(float2 a, float2 b) {
    float2 d;
    asm("add.rn.f32x2 %0, %1, %2;"
        : "=l"(*reinterpret_cast<unsigned long long*>(&d))
        : "l"(*reinterpret_cast<const unsigned long long*>(&a)),
          "l"(*reinterpret_cast<const unsigned long long*>(&b)));
    return d;
}

// ---------------------------------------------------------------------------
// Kernel 1: fused tile pass. Block = A-tile (2048 queries, 8/thread regs)
// x B-slice (128 refs smem). Full squared distances ONCE; row mins in regs,
// col mins in per-warp smem (skewed index: conflict/race free). Block results
// folded into g_minbits via encoded atomicMax (RED.MAX, no return).
// grid = BATCH * NAT * NBS = 256 blocks x 256 threads (all co-resident).
// ---------------------------------------------------------------------------
__global__ void __launch_bounds__(TPB) min_kernel(const float* __restrict__ A,
                                                  const float* __restrict__ B,
                                                  float* __restrict__ out) {
    __shared__ float4 sB1[BSL];        // (bx,bx,by,by)
    __shared__ float4 sB2[BSL];        // (bz,bz,bn,bn)
    __shared__ float  cmin[8][BSL];    // per-warp col partial mins

    int bid = blockIdx.x;
    int bs  = bid & (NBS - 1);         // B slice 0..31
    int at  = (bid >> 5) & (NAT - 1);  // A tile 0..1
    int b   = bid >> 6;                // batch

    int t = threadIdx.x;
    int w = t >> 5;
    if (bid == 0 && t == 0) { out[0] = 0.0f; out[1] = 0.0f; }

    const float* Ab = A + b * 3 * NPTS;  // gts (tgt)
    const float* Bb = B + b * 3 * NPTS;  // preds (src_transformed)

    if (t < BSL) {
        int j = bs * BSL + t;
        float bx = Bb[j], by = Bb[NPTS + j], bz = Bb[2 * NPTS + j];
        float bn = fmaf(bx, bx, fmaf(by, by, bz * bz));
        sB1[t] = make_float4(bx, bx, by, by);
        sB2[t] = make_float4(bz, bz, bn, bn);
    }
    for (int idx = t; idx < 8 * BSL; idx += TPB) (&cmin[0][0])[idx] = INFV;
    __syncthreads();

    // 8 queries per thread as 4 packed pairs; x/y/z pre-scaled by -2, norm kept.
    float2 qx[4], qy[4], qz[4], qn[4];
    float  m[8];
    int i0 = at * ATILE + t;
    #pragma unroll
    for (int jp = 0; jp < 4; jp++) {
        int ia = i0 + (2 * jp) * TPB;
        int ic = i0 + (2 * jp + 1) * TPB;
        float ax = Ab[ia], ay = Ab[NPTS + ia], az = Ab[2 * NPTS + ia];
        float cx = Ab[ic], cy = Ab[NPTS + ic], cz = Ab[2 * NPTS + ic];
        float na = fmaf(ax, ax, fmaf(ay, ay, az * az));
        float nc = fmaf(cx, cx, fmaf(cy, cy, cz * cz));
        qx[jp] = make_float2(-2.0f * ax, -2.0f * cx);
        qy[jp] = make_float2(-2.0f * ay, -2.0f * cy);
        qz[jp] = make_float2(-2.0f * az, -2.0f * cz);
        qn[jp] = make_float2(na, nc);
        m[2 * jp] = INFV; m[2 * jp + 1] = INFV;
    }

    #pragma unroll 4
    for (int i = 0; i < BSL; i++) {
        int r = (t + i) & (BSL - 1);   // skewed: lanes hit distinct refs/banks
        float4 b1 = sB1[r];
        float4 b2 = sB2[r];
        float2 rx = make_float2(b1.x, b1.y);
        float2 ry = make_float2(b1.z, b1.w);
        float2 rz = make_float2(b2.x, b2.y);
        float2 rn = make_float2(b2.z, b2.w);

        float p[4];
        #pragma unroll
        for (int jp = 0; jp < 4; jp++) {
            float2 bias = fadd2(qn[jp], rn);  // qn + rn: full-dist bias
            float2 d2 = ffma2(qx[jp], rx, ffma2(qy[jp], ry, ffma2(qz[jp], rz, bias)));
            m[2 * jp]     = fminf(m[2 * jp],     d2.x);
            m[2 * jp + 1] = fminf(m[2 * jp + 1], d2.y);
            p[jp] = fminf(d2.x, d2.y);
        }
        float v = fminf(fminf(p[0], p[1]), fminf(p[2], p[3]));
        cmin[w][r] = fminf(cmin[w][r], v);
    }
    __syncthreads();

    // Row mins: encoded max-reduce (RED.MAX, no return).
    unsigned* rowm = g_minbits + b * NPTS;
    #pragma unroll
    for (int u = 0; u < 8; u++)
        atomicMax(&rowm[i0 + u * TPB], enc_desc(m[u]));

    // Col mins: merge 8 warp arrays, one RED per B-point of this slice.
    if (t < BSL) {
        float cv = cmin[0][t];
        #pragma unroll
        for (int ww = 1; ww < 8; ww++) cv = fminf(cv, cmin[ww][t]);
        atomicMax(&g_minbits[BATCH * NPTS + b * NPTS + bs * BSL + t], enc_desc(cv));
    }
}

// ---------------------------------------------------------------------------
__device__ __forceinline__ float2 block_reduce2(float2 v) {
    __shared__ float2 sh[32];
    int lane = threadIdx.x & 31;
    int wid  = threadIdx.x >> 5;
    #pragma unroll
    for (int o = 16; o; o >>= 1) {
        v.x += __shfl_down_sync(0xffffffffu, v.x, o);
        v.y += __shfl_down_sync(0xffffffffu, v.y, o);
    }
    if (lane == 0) sh[wid] = v;
    __syncthreads();
    if (wid == 0) {
        v = (lane < (int)(blockDim.x >> 5)) ? sh[lane] : make_float2(0.0f, 0.0f);
        #pragma unroll
        for (int o = 16; o; o >>= 1) {
            v.x += __shfl_down_sync(0xffffffffu, v.x, o);
            v.y += __shfl_down_sync(0xffffffffu, v.y, o);
        }
    }
    return v;
}

// ---------------------------------------------------------------------------
// Kernel 2: finalize. All global loads issued up-front and independent
// (explicit predicated knn loads instead of a trip-count-1.5 loop), so the
// whole thread costs ~one memory-latency round.
// grid = 256 blocks x 128 threads = 32768 (one per min entry).
// ---------------------------------------------------------------------------
__global__ void __launch_bounds__(128) fin_kernel(const float* __restrict__ sk,
                                                  const float* __restrict__ tk,
                                                  const float* __restrict__ Rot,
                                                  const float* __restrict__ Tr,
                                                  const float* __restrict__ sknn,
                                                  const float* __restrict__ tknn,
                                                  float* __restrict__ out) {
    int i = blockIdx.x * 128 + threadIdx.x;  // 0..32767

    // -- issue all loads early, all independent --
    unsigned e = g_minbits[i];

    const int TOT4 = BATCH * 3 * KPN * KNN / 4;  // 49152
    const float4* s4 = (const float4*)sknn;
    const float4* t4 = (const float4*)tknn;
    float4 a0 = s4[i];
    float4 b0 = t4[i];
    bool has2 = (i + 32768) < TOT4;              // i < 16384
    int j2 = has2 ? (i + 32768) : i;
    float4 a1 = s4[j2];
    float4 b1 = t4[j2];

    g_minbits[i] = 0;                            // reset for next replay

    // -- huber on the min distance --
    float d = dec_desc(e);
    const float c = 0.01f;
    float h = (d < c) ? (0.5f * d * d) : fmaf(c, d, -0.5f * c * c);

    // -- knn consensus --
    float d0 = a0.x - b0.x, d1 = a0.y - b0.y, d2 = a0.z - b0.z, d3 = a0.w - b0.w;
    float acc = fmaf(d0, d0, fmaf(d1, d1, fmaf(d2, d2, d3 * d3)));
    if (has2) {
        float e0 = a1.x - b1.x, e1 = a1.y - b1.y, e2 = a1.z - b1.z, e3 = a1.w - b1.w;
        acc += fmaf(e0, e0, fmaf(e1, e1, fmaf(e2, e2, e3 * e3)));
    }
    acc *= (1.0f / (float)KNN);

    // -- keypoint transform loss (first 2048 threads) --
    if (i < BATCH * KPN) {
        int kb = i >> 9;
        int p  = i & (KPN - 1);
        const float* Rb  = Rot + kb * 9;
        const float* tb  = Tr + kb * 3;
        const float* skb = sk + kb * 3 * KPN;
        const float* tkb = tk + kb * 3 * KPN;
        float px = skb[p], py = skb[KPN + p], pz = skb[2 * KPN + p];
        #pragma unroll
        for (int cd = 0; cd < 3; cd++) {
            float wv = fmaf(Rb[cd * 3 + 0], px,
                       fmaf(Rb[cd * 3 + 1], py,
                       fmaf(Rb[cd * 3 + 2], pz, tb[cd])))
                       - tkb[cd * KPN + p];
            acc = fmaf(wv, wv, acc);
        }
    }

    float2 sums = block_reduce2(make_float2(acc, h));
    if (threadIdx.x == 0) {
        atomicAdd(&out[0], sums.x);
        atomicAdd(&out[1], sums.y);
    }
}

// ---------------------------------------------------------------------------
extern "C" void kernel_launch(void* const* d_in, const int* in_sizes, int n_in,
                              void* d_out, int out_size) {
    const float* src_kp  = (const float*)d_in[0];  // (B,3,KP)
    const float* tgt_kp  = (const float*)d_in[1];  // (B,3,KP)
    const float* rot     = (const float*)d_in[2];  // (B,3,3)
    const float* tra     = (const float*)d_in[3];  // (B,3)
    const float* src_knn = (const float*)d_in[4];  // (B,3,KP,K)
    const float* tgt_knn = (const float*)d_in[5];  // (B,3,KP,K)
    // d_in[6] = k (constant 32, hardcoded)
    const float* src_tr  = (const float*)d_in[7];  // (B,3,N) preds
    const float* tgt     = (const float*)d_in[8];  // (B,3,N) gts
    float* out = (float*)d_out;                    // out[0]=nbh, out[1]=gal

    min_kernel<<<BATCH * NAT * NBS, TPB>>>(tgt, src_tr, out);
    fin_kernel<<<256, 128>>>(src_kp, tgt_kp, rot, tra, src_knn, tgt_knn, out);
}